// round 16
// baseline (speedup 1.0000x reference)
#include <cuda_runtime.h>
#include <cuda_fp16.h>
#include <cstdint>

#define NN 100000
#define NE 1600000
#define HD 64
#define IND 5
#define OUTD 4
#define BN_EPS 1e-5f
#define TS 65   // padded tile row stride (floats)
#define SCAN_NBLK 98   // cdiv(100000, 1024)

// ---------------- scratch (static; no allocation allowed) ----------------
__device__ __align__(16) __half g_xwh[(size_t)NN * HD];   // fp16 dv-prescaled features
__device__ float  g_agg[(size_t)NN * HD];
__device__ int    g_cnt_s[NN], g_cnt_t[NN];
__device__ int    g_start_s[NN], g_start_t[NN];
__device__ int    g_cur_s[NN],  g_cur_t[NN];
__device__ float  g_dv_s[NN],  g_dv_t[NN];
__device__ int    g_adj_s[NE], g_adj_t[NE];      // row index per edge, grouped by col
__device__ int    g_bsum[256];                   // [2][128] raw block sums for scan
__device__ double g_sum[HD], g_sumsq[HD];

static inline int cdiv(long long a, int b) { return (int)((a + b - 1) / b); }

// 8 fp16 (uint4) -> fp32 add into acc[8]
__device__ __forceinline__ void add_h8(float* acc, uint4 v) {
    __half2 h; float2 f;
    h = *reinterpret_cast<__half2*>(&v.x); f = __half22float2(h);
    acc[0] += f.x; acc[1] += f.y;
    h = *reinterpret_cast<__half2*>(&v.y); f = __half22float2(h);
    acc[2] += f.x; acc[3] += f.y;
    h = *reinterpret_cast<__half2*>(&v.z); f = __half22float2(h);
    acc[4] += f.x; acc[5] += f.y;
    h = *reinterpret_cast<__half2*>(&v.w); f = __half22float2(h);
    acc[6] += f.x; acc[7] += f.y;
}

// ---------------- CSR build (merged two-graph kernels, R11 form) ----------------
// cnt arrays pre-zeroed (static init first call; fc_kernel epilogue after)
__global__ void count_kernel(const int* __restrict__ s_cols, const int* __restrict__ t_cols,
                             int* __restrict__ cnt_s, int* __restrict__ cnt_t, int nE) {
    int e = blockIdx.x * blockDim.x + threadIdx.x;
    if (e < nE) {
        atomicAdd(&cnt_s[s_cols[e]], 1);
        atomicAdd(&cnt_t[t_cols[e]], 1);
    }
}

// per-block scan of counts + dinv; gridDim = (SCAN_NBLK, 2)
__global__ void scan1_kernel(const int* __restrict__ cnt_s, int* __restrict__ start_s,
                             const int* __restrict__ cnt_t, int* __restrict__ start_t,
                             float* __restrict__ dv_s, float* __restrict__ dv_t,
                             int* __restrict__ bsum, int n) {
    const int* cnt = blockIdx.y ? cnt_t : cnt_s;
    int* start = blockIdx.y ? start_t : start_s;
    float* dv = blockIdx.y ? dv_t : dv_s;
    __shared__ int sh[1024];
    int t = threadIdx.x;
    int i = blockIdx.x * 1024 + t;
    int v = (i < n) ? cnt[i] : 0;
    if (i < n) dv[i] = rsqrtf((float)v + 1.0f);
    sh[t] = v;
    __syncthreads();
    #pragma unroll
    for (int off = 1; off < 1024; off <<= 1) {
        int x = (t >= off) ? sh[t - off] : 0;
        __syncthreads();
        sh[t] += x;
        __syncthreads();
    }
    if (i < n) start[i] = sh[t] - v;   // exclusive within block
    if (t == 1023) bsum[blockIdx.y * 128 + blockIdx.x] = sh[1023];
}

// combined block-offset computation + apply; gridDim = (cdiv(n,256), 2)
__global__ void scan23_kernel(int* __restrict__ start_s, int* __restrict__ cur_s,
                              int* __restrict__ start_t, int* __restrict__ cur_t,
                              const int* __restrict__ bsum, int n) {
    int g = blockIdx.y;
    int* start = g ? start_t : start_s;
    int* cur   = g ? cur_t   : cur_s;
    int t = threadIdx.x;
    int bi = blockIdx.x >> 2;   // 1024-element chunk index of this 256-block
    __shared__ int sh[128];
    if (t < 128) sh[t] = (t < bi) ? bsum[g * 128 + t] : 0;
    __syncthreads();
    #pragma unroll
    for (int off = 64; off > 0; off >>= 1) {
        if (t < off) sh[t] += sh[t + off];
        __syncthreads();
    }
    int offset = sh[0];
    int i = blockIdx.x * 256 + t;
    if (i < n) {
        int val = start[i] + offset;
        start[i] = val;
        cur[i] = val;
    }
}

// both graphs in one pass; scatter only the row index (4 B)
__global__ void place_kernel(const int* __restrict__ s_rows, const int* __restrict__ s_cols,
                             const int* __restrict__ t_rows, const int* __restrict__ t_cols,
                             int* __restrict__ cur_s, int* __restrict__ cur_t,
                             int* __restrict__ adj_s, int* __restrict__ adj_t, int nE) {
    int e = blockIdx.x * blockDim.x + threadIdx.x;
    if (e >= nE) return;
    {
        int pos = atomicAdd(&cur_s[s_cols[e]], 1);
        adj_s[pos] = s_rows[e];
    }
    {
        int pos = atomicAdd(&cur_t[t_cols[e]], 1);
        adj_t[pos] = t_rows[e];
    }
}

// ---------------- layer 1 projection: xs = dv .* (x @ w1), fp16 out ----------------
__global__ void xw1_kernel(const float* __restrict__ x, const float* __restrict__ w,
                           const float* __restrict__ dv, __half* __restrict__ outh, int n) {
    __shared__ float Ws[IND * HD];
    int t = threadIdx.x;
    for (int i = t; i < IND * HD; i += blockDim.x) Ws[i] = w[i];
    __syncthreads();
    int idx = blockIdx.x * blockDim.x + t;
    int node = idx >> 4, q = idx & 15;
    if (node >= n) return;
    float xr[IND];
    #pragma unroll
    for (int k = 0; k < IND; k++) xr[k] = __ldg(&x[(size_t)node * IND + k]);
    float4 a = make_float4(0.f, 0.f, 0.f, 0.f);
    #pragma unroll
    for (int k = 0; k < IND; k++) {
        const float* wr = &Ws[k * HD + q * 4];
        a.x = fmaf(xr[k], wr[0], a.x);
        a.y = fmaf(xr[k], wr[1], a.y);
        a.z = fmaf(xr[k], wr[2], a.z);
        a.w = fmaf(xr[k], wr[3], a.w);
    }
    float d = __ldg(&dv[node]);
    __half2 h0 = __floats2half2_rn(d * a.x, d * a.y);
    __half2 h1 = __floats2half2_rn(d * a.z, d * a.w);
    uint2 o;
    o.x = *reinterpret_cast<unsigned*>(&h0);
    o.y = *reinterpret_cast<unsigned*>(&h1);
    ((uint2*)outh)[(size_t)node * 16 + q] = o;
}

// ---------------- aggregation (gather over CSR, weightless) — R11 form ----------------
// agg[c] = b + dv[c] * ( sum_{edges into c} xs[row] + xs[c] )
// 8 lanes per node (16 B each); unroll-4 batched loads; fp32 accumulation.
__global__ void __launch_bounds__(256)
gather_kernel(const int* __restrict__ adj, const int* __restrict__ start,
              const int* __restrict__ cnt, const float* __restrict__ dinv,
              const __half* __restrict__ xwh, const float* __restrict__ bias,
              float* __restrict__ agg, int n) {
    int t = threadIdx.x;
    if (blockIdx.x == 0 && t < HD) { g_sum[t] = 0.0; g_sumsq[t] = 0.0; }
    int idx = blockIdx.x * 256 + t;
    int node = idx >> 3, q = idx & 7;
    if (node >= n) return;

    const uint4* xw4 = (const uint4*)xwh;
    float acc[8];
    {
        uint4 selfv = __ldg(&xw4[(size_t)node * 8 + q]);
        __half2 h; float2 f;
        h = *reinterpret_cast<__half2*>(&selfv.x); f = __half22float2(h);
        acc[0] = f.x; acc[1] = f.y;
        h = *reinterpret_cast<__half2*>(&selfv.y); f = __half22float2(h);
        acc[2] = f.x; acc[3] = f.y;
        h = *reinterpret_cast<__half2*>(&selfv.z); f = __half22float2(h);
        acc[4] = f.x; acc[5] = f.y;
        h = *reinterpret_cast<__half2*>(&selfv.w); f = __half22float2(h);
        acc[6] = f.x; acc[7] = f.y;
    }

    int p  = start[node];
    int p1 = p + cnt[node];
    for (; p + 4 <= p1; p += 4) {
        int r0 = __ldg(&adj[p]);
        int r1 = __ldg(&adj[p + 1]);
        int r2 = __ldg(&adj[p + 2]);
        int r3 = __ldg(&adj[p + 3]);
        uint4 v0 = __ldg(&xw4[(size_t)r0 * 8 + q]);
        uint4 v1 = __ldg(&xw4[(size_t)r1 * 8 + q]);
        uint4 v2 = __ldg(&xw4[(size_t)r2 * 8 + q]);
        uint4 v3 = __ldg(&xw4[(size_t)r3 * 8 + q]);
        add_h8(acc, v0);
        add_h8(acc, v1);
        add_h8(acc, v2);
        add_h8(acc, v3);
    }
    for (; p < p1; p++) {
        int r = __ldg(&adj[p]);
        add_h8(acc, __ldg(&xw4[(size_t)r * 8 + q]));
    }

    float d = __ldg(&dinv[node]);
    float4 b0 = __ldg(&((const float4*)bias)[q * 2]);
    float4 b1 = __ldg(&((const float4*)bias)[q * 2 + 1]);
    float4* dst = (float4*)(agg + (size_t)node * HD + q * 8);
    dst[0] = make_float4(fmaf(d, acc[0], b0.x), fmaf(d, acc[1], b0.y),
                         fmaf(d, acc[2], b0.z), fmaf(d, acc[3], b0.w));
    dst[1] = make_float4(fmaf(d, acc[4], b1.x), fmaf(d, acc[5], b1.y),
                         fmaf(d, acc[6], b1.z), fmaf(d, acc[7], b1.w));
}

// ---------------- BN stats: column sums / sumsq (float4 vectorized) ----------------
__global__ void bn_stats_kernel(const float* __restrict__ agg, int n) {
    int t = threadIdx.x;              // 256
    int c4 = t & 15;                  // float4 column group (16 x 4 = 64 cols)
    int sub = t >> 4;                 // 16 row substreams
    float4 s = make_float4(0.f, 0.f, 0.f, 0.f);
    float4 q = make_float4(0.f, 0.f, 0.f, 0.f);
    const float4* agg4 = (const float4*)agg;
    for (int i = blockIdx.x * 16 + sub; i < n; i += gridDim.x * 16) {
        float4 v = __ldg(&agg4[(size_t)i * 16 + c4]);
        s.x += v.x; s.y += v.y; s.z += v.z; s.w += v.w;
        q.x = fmaf(v.x, v.x, q.x);
        q.y = fmaf(v.y, v.y, q.y);
        q.z = fmaf(v.z, v.z, q.z);
        q.w = fmaf(v.w, v.w, q.w);
    }
    __shared__ float4 sh_s[256], sh_q[256];
    sh_s[t] = s; sh_q[t] = q;
    __syncthreads();
    // fold the 16 substreams (t = sub*16 + c4; offsets are multiples of 16)
    #pragma unroll
    for (int off = 128; off >= 16; off >>= 1) {
        if (t < off) {
            float4 a = sh_s[t], b = sh_s[t + off];
            sh_s[t] = make_float4(a.x + b.x, a.y + b.y, a.z + b.z, a.w + b.w);
            float4 c = sh_q[t], d = sh_q[t + off];
            sh_q[t] = make_float4(c.x + d.x, c.y + d.y, c.z + d.z, c.w + d.w);
        }
        __syncthreads();
    }
    if (t < 16) {
        float4 ss = sh_s[t], qq = sh_q[t];
        atomicAdd(&g_sum[t * 4 + 0], (double)ss.x);
        atomicAdd(&g_sum[t * 4 + 1], (double)ss.y);
        atomicAdd(&g_sum[t * 4 + 2], (double)ss.z);
        atomicAdd(&g_sum[t * 4 + 3], (double)ss.w);
        atomicAdd(&g_sumsq[t * 4 + 0], (double)qq.x);
        atomicAdd(&g_sumsq[t * 4 + 1], (double)qq.y);
        atomicAdd(&g_sumsq[t * 4 + 2], (double)qq.z);
        atomicAdd(&g_sumsq[t * 4 + 3], (double)qq.w);
    }
}

// ---------------- fused BN-finalize+BN+ReLU+GEMM, dv-prescaled fp16 out ----------------
__global__ void __launch_bounds__(128)
xw_fused_kernel(const float* __restrict__ in, const float* __restrict__ W,
                const float* __restrict__ gg, const float* __restrict__ be,
                const float* __restrict__ dv, __half* __restrict__ outh, int n) {
    __shared__ float tile[64 * TS];
    __shared__ float Ws[HD * HD];
    __shared__ float as[HD], cs[HD];
    int t = threadIdx.x;
    for (int i = t; i < HD * HD; i += 128) Ws[i] = W[i];
    if (t < HD) {
        double mean = g_sum[t] / n;
        double var  = g_sumsq[t] / n - mean * mean;
        float a = gg[t] * rsqrtf((float)var + BN_EPS);
        as[t] = a;
        cs[t] = be[t] - (float)mean * a;
    }

    int base = blockIdx.x * 64;
    int nv = min(64, n - base);
    const float4* in4 = (const float4*)(in + (size_t)base * HD);
    for (int i = t; i < nv * 16; i += 128) {
        float4 v = __ldg(&in4[i]);
        float* p = &tile[(i >> 4) * TS + (i & 15) * 4];
        p[0] = v.x; p[1] = v.y; p[2] = v.z; p[3] = v.w;
    }
    __syncthreads();

    int node = t >> 1, h = t & 1;
    if ((base + node) >= n) return;
    float acc[32];
    #pragma unroll
    for (int j = 0; j < 32; j++) acc[j] = 0.f;
    {
        const float* row = &tile[node * TS];
        const float* wb  = &Ws[h * 32];
        #pragma unroll 4
        for (int k = 0; k < HD; k++) {
            float v = fmaxf(fmaf(row[k], as[k], cs[k]), 0.f);
            #pragma unroll
            for (int j = 0; j < 32; j++) acc[j] = fmaf(v, wb[k * HD + j], acc[j]);
        }
    }
    float d = __ldg(&dv[base + node]);
    unsigned packed[16];
    #pragma unroll
    for (int j = 0; j < 16; j++) {
        __half2 hv = __floats2half2_rn(d * acc[2 * j], d * acc[2 * j + 1]);
        packed[j] = *reinterpret_cast<unsigned*>(&hv);
    }
    uint4* dst = (uint4*)(outh + (size_t)(base + node) * HD + h * 32);
    #pragma unroll
    for (int j = 0; j < 4; j++)
        dst[j] = make_uint4(packed[4*j], packed[4*j+1], packed[4*j+2], packed[4*j+3]);
}

// ---------------- final FC (+BN finalize, + cnt re-zero for next call) ----------------
__global__ void __launch_bounds__(128)
fc_kernel(const float* __restrict__ agg, const float* __restrict__ wfc,
          const float* __restrict__ bfc, const float* __restrict__ gg,
          const float* __restrict__ be, float* __restrict__ out, int n) {
    __shared__ float tile[128 * TS];
    __shared__ float Wf[HD * OUTD];
    __shared__ float as[HD], cs[HD];
    int t = threadIdx.x;
    if (t < HD) {
        double mean = g_sum[t] / n;
        double var  = g_sumsq[t] / n - mean * mean;
        float a = gg[t] * rsqrtf((float)var + BN_EPS);
        as[t] = a;
        cs[t] = be[t] - (float)mean * a;
        ((float4*)Wf)[t] = ((const float4*)wfc)[t];
    }

    int base = blockIdx.x * 128;
    // re-zero degree counters for the next kernel_launch invocation
    {
        int i = base + t;
        if (i < n) { g_cnt_s[i] = 0; g_cnt_t[i] = 0; }
    }
    int nv = min(128, n - base);
    const float4* in4 = (const float4*)(agg + (size_t)base * HD);
    for (int i = t; i < nv * 16; i += 128) {
        float4 v = __ldg(&in4[i]);
        float* p = &tile[(i >> 4) * TS + (i & 15) * 4];
        p[0] = v.x; p[1] = v.y; p[2] = v.z; p[3] = v.w;
    }
    __syncthreads();
    if (t < nv) {
        float a0 = __ldg(&bfc[0]), a1 = __ldg(&bfc[1]);
        float a2 = __ldg(&bfc[2]), a3 = __ldg(&bfc[3]);
        const float* row = &tile[t * TS];
        #pragma unroll 8
        for (int k = 0; k < HD; k++) {
            float v = fmaxf(fmaf(row[k], as[k], cs[k]), 0.f);
            a0 = fmaf(v, Wf[k * 4 + 0], a0);
            a1 = fmaf(v, Wf[k * 4 + 1], a1);
            a2 = fmaf(v, Wf[k * 4 + 2], a2);
            a3 = fmaf(v, Wf[k * 4 + 3], a3);
        }
        ((float4*)out)[base + t] = make_float4(a0, a1, a2, a3);
    }
}

// ---------------- host orchestration ----------------
extern "C" void kernel_launch(void* const* d_in, const int* in_sizes, int n_in,
                              void* d_out, int out_size) {
    const float* x   = (const float*)d_in[0];
    const int*   sei = (const int*)d_in[1];
    const int*   tei = (const int*)d_in[2];
    const float* w1  = (const float*)d_in[3];
    const float* b1  = (const float*)d_in[4];
    const float* g1  = (const float*)d_in[5];
    const float* be1 = (const float*)d_in[6];
    const float* w2  = (const float*)d_in[7];
    const float* b2  = (const float*)d_in[8];
    const float* g2  = (const float*)d_in[9];
    const float* be2 = (const float*)d_in[10];
    const float* w3  = (const float*)d_in[11];
    const float* b3  = (const float*)d_in[12];
    const float* g3  = (const float*)d_in[13];
    const float* be3 = (const float*)d_in[14];
    const float* w4  = (const float*)d_in[15];
    const float* b4  = (const float*)d_in[16];
    const float* g4  = (const float*)d_in[17];
    const float* be4 = (const float*)d_in[18];
    const float* wfc = (const float*)d_in[19];
    const float* bfc = (const float*)d_in[20];
    float* out = (float*)d_out;

    const int n = in_sizes[0] / IND;   // 100000
    const int e = in_sizes[1] / 2;     // 1600000
    const int* s_rows = sei;  const int* s_cols = sei + e;
    const int* t_rows = tei;  const int* t_cols = tei + e;

    int *cnt_s, *cnt_t, *start_s, *start_t, *cur_s, *cur_t, *bsum;
    float *dv_s, *dv_t, *agg;
    __half* xwh;
    int *adj_s, *adj_t;
    cudaGetSymbolAddress((void**)&cnt_s, g_cnt_s);
    cudaGetSymbolAddress((void**)&cnt_t, g_cnt_t);
    cudaGetSymbolAddress((void**)&start_s, g_start_s);
    cudaGetSymbolAddress((void**)&start_t, g_start_t);
    cudaGetSymbolAddress((void**)&cur_s, g_cur_s);
    cudaGetSymbolAddress((void**)&cur_t, g_cur_t);
    cudaGetSymbolAddress((void**)&dv_s, g_dv_s);
    cudaGetSymbolAddress((void**)&dv_t, g_dv_t);
    cudaGetSymbolAddress((void**)&xwh, g_xwh);
    cudaGetSymbolAddress((void**)&agg, g_agg);
    cudaGetSymbolAddress((void**)&adj_s, g_adj_s);
    cudaGetSymbolAddress((void**)&adj_t, g_adj_t);
    cudaGetSymbolAddress((void**)&bsum, g_bsum);

    const int eg   = cdiv(e, 256);
    const int ng16 = cdiv((long long)n * 16, 256);
    const int ng8  = cdiv((long long)n * 8, 256);

    // ---- CSR build (merged two-graph kernels; cnt pre-zeroed) ----
    count_kernel<<<eg, 256>>>(s_cols, t_cols, cnt_s, cnt_t, e);
    scan1_kernel<<<dim3(SCAN_NBLK, 2), 1024>>>(cnt_s, start_s, cnt_t, start_t,
                                               dv_s, dv_t, bsum, n);
    scan23_kernel<<<dim3(cdiv(n, 256), 2), 256>>>(start_s, cur_s, start_t, cur_t, bsum, n);
    place_kernel<<<eg, 256>>>(s_rows, s_cols, t_rows, t_cols,
                              cur_s, cur_t, adj_s, adj_t, e);

    // ---- layer 1 (spatial) ----
    xw1_kernel<<<ng16, 256>>>(x, w1, dv_s, xwh, n);
    gather_kernel<<<ng8, 256>>>(adj_s, start_s, cnt_s, dv_s, xwh, b1, agg, n);
    bn_stats_kernel<<<512, 256>>>(agg, n);

    // ---- layer 2 (spatial) ----
    xw_fused_kernel<<<cdiv(n, 64), 128>>>(agg, w2, g1, be1, dv_s, xwh, n);
    gather_kernel<<<ng8, 256>>>(adj_s, start_s, cnt_s, dv_s, xwh, b2, agg, n);
    bn_stats_kernel<<<512, 256>>>(agg, n);

    // ---- layer 3 (temporal) ----
    xw_fused_kernel<<<cdiv(n, 64), 128>>>(agg, w3, g2, be2, dv_t, xwh, n);
    gather_kernel<<<ng8, 256>>>(adj_t, start_t, cnt_t, dv_t, xwh, b3, agg, n);
    bn_stats_kernel<<<512, 256>>>(agg, n);

    // ---- layer 4 (temporal) ----
    xw_fused_kernel<<<cdiv(n, 64), 128>>>(agg, w4, g3, be3, dv_t, xwh, n);
    gather_kernel<<<ng8, 256>>>(adj_t, start_t, cnt_t, dv_t, xwh, b4, agg, n);
    bn_stats_kernel<<<512, 256>>>(agg, n);

    // ---- final FC (+BN finalize of layer 4, + cnt re-zero) ----
    fc_kernel<<<cdiv(n, 128), 128>>>(agg, wfc, bfc, g4, be4, out, n);
}

// round 17
// speedup vs baseline: 1.2158x; 1.2158x over previous
#include <cuda_runtime.h>
#include <cuda_fp16.h>
#include <cstdint>

#define NN 100000
#define NE 1600000
#define HD 64
#define IND 5
#define OUTD 4
#define BN_EPS 1e-5f
#define TS 65   // padded tile row stride (floats)
#define SCAN_NBLK 98   // cdiv(100000, 1024)

// ---------------- scratch (static; no allocation allowed) ----------------
__device__ __align__(16) __half g_xwh[(size_t)NN * HD];   // fp16 dv-prescaled features
__device__ float  g_agg[(size_t)NN * HD];
__device__ int    g_cnt_s[NN], g_cnt_t[NN];
__device__ int    g_start_s[NN], g_start_t[NN];
__device__ int    g_cur_s[NN],  g_cur_t[NN];
__device__ float  g_dv_s[NN],  g_dv_t[NN];
__device__ int    g_adj_s[NE], g_adj_t[NE];      // row index per edge, grouped by col
__device__ int    g_bsum[256];                   // [2][128] raw block sums for scan
__device__ double g_sum[HD], g_sumsq[HD];

static inline int cdiv(long long a, int b) { return (int)((a + b - 1) / b); }

// 8 fp16 (uint4) -> fp32 add into acc[8]
__device__ __forceinline__ void add_h8(float* acc, uint4 v) {
    __half2 h; float2 f;
    h = *reinterpret_cast<__half2*>(&v.x); f = __half22float2(h);
    acc[0] += f.x; acc[1] += f.y;
    h = *reinterpret_cast<__half2*>(&v.y); f = __half22float2(h);
    acc[2] += f.x; acc[3] += f.y;
    h = *reinterpret_cast<__half2*>(&v.z); f = __half22float2(h);
    acc[4] += f.x; acc[5] += f.y;
    h = *reinterpret_cast<__half2*>(&v.w); f = __half22float2(h);
    acc[6] += f.x; acc[7] += f.y;
}

// ---------------- CSR build (merged two-graph kernels, R11 form) ----------------
// cnt arrays pre-zeroed (static init first call; fc_kernel epilogue after)
__global__ void count_kernel(const int* __restrict__ s_cols, const int* __restrict__ t_cols,
                             int* __restrict__ cnt_s, int* __restrict__ cnt_t, int nE) {
    int e = blockIdx.x * blockDim.x + threadIdx.x;
    if (e < nE) {
        atomicAdd(&cnt_s[s_cols[e]], 1);
        atomicAdd(&cnt_t[t_cols[e]], 1);
    }
}

// per-block scan of counts + dinv; gridDim = (SCAN_NBLK, 2)
__global__ void scan1_kernel(const int* __restrict__ cnt_s, int* __restrict__ start_s,
                             const int* __restrict__ cnt_t, int* __restrict__ start_t,
                             float* __restrict__ dv_s, float* __restrict__ dv_t,
                             int* __restrict__ bsum, int n) {
    const int* cnt = blockIdx.y ? cnt_t : cnt_s;
    int* start = blockIdx.y ? start_t : start_s;
    float* dv = blockIdx.y ? dv_t : dv_s;
    __shared__ int sh[1024];
    int t = threadIdx.x;
    int i = blockIdx.x * 1024 + t;
    int v = (i < n) ? cnt[i] : 0;
    if (i < n) dv[i] = rsqrtf((float)v + 1.0f);
    sh[t] = v;
    __syncthreads();
    #pragma unroll
    for (int off = 1; off < 1024; off <<= 1) {
        int x = (t >= off) ? sh[t - off] : 0;
        __syncthreads();
        sh[t] += x;
        __syncthreads();
    }
    if (i < n) start[i] = sh[t] - v;   // exclusive within block
    if (t == 1023) bsum[blockIdx.y * 128 + blockIdx.x] = sh[1023];
}

// combined block-offset computation + apply; gridDim = (cdiv(n,256), 2)
__global__ void scan23_kernel(int* __restrict__ start_s, int* __restrict__ cur_s,
                              int* __restrict__ start_t, int* __restrict__ cur_t,
                              const int* __restrict__ bsum, int n) {
    int g = blockIdx.y;
    int* start = g ? start_t : start_s;
    int* cur   = g ? cur_t   : cur_s;
    int t = threadIdx.x;
    int bi = blockIdx.x >> 2;   // 1024-element chunk index of this 256-block
    __shared__ int sh[128];
    if (t < 128) sh[t] = (t < bi) ? bsum[g * 128 + t] : 0;
    __syncthreads();
    #pragma unroll
    for (int off = 64; off > 0; off >>= 1) {
        if (t < off) sh[t] += sh[t + off];
        __syncthreads();
    }
    int offset = sh[0];
    int i = blockIdx.x * 256 + t;
    if (i < n) {
        int val = start[i] + offset;
        start[i] = val;
        cur[i] = val;
    }
}

// both graphs in one pass; scatter only the row index (4 B)
__global__ void place_kernel(const int* __restrict__ s_rows, const int* __restrict__ s_cols,
                             const int* __restrict__ t_rows, const int* __restrict__ t_cols,
                             int* __restrict__ cur_s, int* __restrict__ cur_t,
                             int* __restrict__ adj_s, int* __restrict__ adj_t, int nE) {
    int e = blockIdx.x * blockDim.x + threadIdx.x;
    if (e >= nE) return;
    {
        int pos = atomicAdd(&cur_s[s_cols[e]], 1);
        adj_s[pos] = s_rows[e];
    }
    {
        int pos = atomicAdd(&cur_t[t_cols[e]], 1);
        adj_t[pos] = t_rows[e];
    }
}

// ---------------- layer 1 projection: xs = dv .* (x @ w1), fp16 out ----------------
__global__ void xw1_kernel(const float* __restrict__ x, const float* __restrict__ w,
                           const float* __restrict__ dv, __half* __restrict__ outh, int n) {
    __shared__ float Ws[IND * HD];
    int t = threadIdx.x;
    for (int i = t; i < IND * HD; i += blockDim.x) Ws[i] = w[i];
    __syncthreads();
    int idx = blockIdx.x * blockDim.x + t;
    int node = idx >> 4, q = idx & 15;
    if (node >= n) return;
    float xr[IND];
    #pragma unroll
    for (int k = 0; k < IND; k++) xr[k] = __ldg(&x[(size_t)node * IND + k]);
    float4 a = make_float4(0.f, 0.f, 0.f, 0.f);
    #pragma unroll
    for (int k = 0; k < IND; k++) {
        const float* wr = &Ws[k * HD + q * 4];
        a.x = fmaf(xr[k], wr[0], a.x);
        a.y = fmaf(xr[k], wr[1], a.y);
        a.z = fmaf(xr[k], wr[2], a.z);
        a.w = fmaf(xr[k], wr[3], a.w);
    }
    float d = __ldg(&dv[node]);
    __half2 h0 = __floats2half2_rn(d * a.x, d * a.y);
    __half2 h1 = __floats2half2_rn(d * a.z, d * a.w);
    uint2 o;
    o.x = *reinterpret_cast<unsigned*>(&h0);
    o.y = *reinterpret_cast<unsigned*>(&h1);
    ((uint2*)outh)[(size_t)node * 16 + q] = o;
}

// ---------------- aggregation (gather over CSR, weightless) — R11 form ----------------
// agg[c] = b + dv[c] * ( sum_{edges into c} xs[row] + xs[c] )
// 8 lanes per node (16 B each); unroll-4 batched loads; fp32 accumulation.
__global__ void __launch_bounds__(256)
gather_kernel(const int* __restrict__ adj, const int* __restrict__ start,
              const int* __restrict__ cnt, const float* __restrict__ dinv,
              const __half* __restrict__ xwh, const float* __restrict__ bias,
              float* __restrict__ agg, int n) {
    int t = threadIdx.x;
    if (blockIdx.x == 0 && t < HD) { g_sum[t] = 0.0; g_sumsq[t] = 0.0; }
    int idx = blockIdx.x * 256 + t;
    int node = idx >> 3, q = idx & 7;
    if (node >= n) return;

    const uint4* xw4 = (const uint4*)xwh;
    float acc[8];
    {
        uint4 selfv = __ldg(&xw4[(size_t)node * 8 + q]);
        __half2 h; float2 f;
        h = *reinterpret_cast<__half2*>(&selfv.x); f = __half22float2(h);
        acc[0] = f.x; acc[1] = f.y;
        h = *reinterpret_cast<__half2*>(&selfv.y); f = __half22float2(h);
        acc[2] = f.x; acc[3] = f.y;
        h = *reinterpret_cast<__half2*>(&selfv.z); f = __half22float2(h);
        acc[4] = f.x; acc[5] = f.y;
        h = *reinterpret_cast<__half2*>(&selfv.w); f = __half22float2(h);
        acc[6] = f.x; acc[7] = f.y;
    }

    int p  = start[node];
    int p1 = p + cnt[node];
    for (; p + 4 <= p1; p += 4) {
        int r0 = __ldg(&adj[p]);
        int r1 = __ldg(&adj[p + 1]);
        int r2 = __ldg(&adj[p + 2]);
        int r3 = __ldg(&adj[p + 3]);
        uint4 v0 = __ldg(&xw4[(size_t)r0 * 8 + q]);
        uint4 v1 = __ldg(&xw4[(size_t)r1 * 8 + q]);
        uint4 v2 = __ldg(&xw4[(size_t)r2 * 8 + q]);
        uint4 v3 = __ldg(&xw4[(size_t)r3 * 8 + q]);
        add_h8(acc, v0);
        add_h8(acc, v1);
        add_h8(acc, v2);
        add_h8(acc, v3);
    }
    for (; p < p1; p++) {
        int r = __ldg(&adj[p]);
        add_h8(acc, __ldg(&xw4[(size_t)r * 8 + q]));
    }

    float d = __ldg(&dinv[node]);
    float4 b0 = __ldg(&((const float4*)bias)[q * 2]);
    float4 b1 = __ldg(&((const float4*)bias)[q * 2 + 1]);
    float4* dst = (float4*)(agg + (size_t)node * HD + q * 8);
    dst[0] = make_float4(fmaf(d, acc[0], b0.x), fmaf(d, acc[1], b0.y),
                         fmaf(d, acc[2], b0.z), fmaf(d, acc[3], b0.w));
    dst[1] = make_float4(fmaf(d, acc[4], b1.x), fmaf(d, acc[5], b1.y),
                         fmaf(d, acc[6], b1.z), fmaf(d, acc[7], b1.w));
}

// ---------------- BN stats: column sums / sumsq (R11 scalar form) ----------------
__global__ void bn_stats_kernel(const float* __restrict__ agg, int n) {
    int t = threadIdx.x;              // 256
    int col = t & 63, sub = t >> 6;
    float s = 0.f, s2 = 0.f;
    for (int i = blockIdx.x * 4 + sub; i < n; i += gridDim.x * 4) {
        float v = agg[(size_t)i * HD + col];
        s += v;
        s2 = fmaf(v, v, s2);
    }
    __shared__ float sh0[256], sh1[256];
    sh0[t] = s; sh1[t] = s2;
    __syncthreads();
    if (sub == 0) {
        double ds  = (double)sh0[t] + sh0[t + 64] + sh0[t + 128] + sh0[t + 192];
        double ds2 = (double)sh1[t] + sh1[t + 64] + sh1[t + 128] + sh1[t + 192];
        atomicAdd(&g_sum[col], ds);
        atomicAdd(&g_sumsq[col], ds2);
    }
}

// ---------------- fused BN-finalize+BN+ReLU+GEMM, 4x8 register blocking ----------------
// block = 128 threads, 64 nodes x 64 outputs. Thread (nt, jt) owns nodes
// nt*4..nt*4+3 and outputs jt*8..jt*8+7: per k = 4 row LDS + 2 LDS.128 of Ws
// for 32 FMAs (2.75x less smem traffic than 1x32 tiling). Accumulation order
// over k per (node, j) is unchanged -> identical numerics.
__global__ void __launch_bounds__(128)
xw_fused_kernel(const float* __restrict__ in, const float* __restrict__ W,
                const float* __restrict__ gg, const float* __restrict__ be,
                const float* __restrict__ dv, __half* __restrict__ outh, int n) {
    __shared__ float tile[64 * TS];
    __shared__ float Ws[HD * HD];
    __shared__ float as[HD], cs[HD];
    int t = threadIdx.x;
    for (int i = t; i < HD * HD; i += 128) Ws[i] = W[i];
    if (t < HD) {
        double mean = g_sum[t] / n;
        double var  = g_sumsq[t] / n - mean * mean;
        float a = gg[t] * rsqrtf((float)var + BN_EPS);
        as[t] = a;
        cs[t] = be[t] - (float)mean * a;
    }

    int base = blockIdx.x * 64;
    int nv = min(64, n - base);
    const float4* in4 = (const float4*)(in + (size_t)base * HD);
    for (int i = t; i < nv * 16; i += 128) {
        float4 v = __ldg(&in4[i]);
        float* p = &tile[(i >> 4) * TS + (i & 15) * 4];
        p[0] = v.x; p[1] = v.y; p[2] = v.z; p[3] = v.w;
    }
    __syncthreads();

    int jt = t & 7;          // output group: cols jt*8 .. jt*8+7
    int nt = t >> 3;         // node group: nodes nt*4 .. nt*4+3
    int n0 = nt * 4;

    float acc[4][8];
    #pragma unroll
    for (int i = 0; i < 4; i++)
        #pragma unroll
        for (int j = 0; j < 8; j++) acc[i][j] = 0.f;

    const float* wsb = &Ws[jt * 8];
    #pragma unroll 4
    for (int k = 0; k < HD; k++) {
        float a_k = as[k], c_k = cs[k];
        float r0 = fmaxf(fmaf(tile[(n0 + 0) * TS + k], a_k, c_k), 0.f);
        float r1 = fmaxf(fmaf(tile[(n0 + 1) * TS + k], a_k, c_k), 0.f);
        float r2 = fmaxf(fmaf(tile[(n0 + 2) * TS + k], a_k, c_k), 0.f);
        float r3 = fmaxf(fmaf(tile[(n0 + 3) * TS + k], a_k, c_k), 0.f);
        float4 w0 = *(const float4*)&wsb[k * HD];
        float4 w1 = *(const float4*)&wsb[k * HD + 4];
        acc[0][0] = fmaf(r0, w0.x, acc[0][0]); acc[0][1] = fmaf(r0, w0.y, acc[0][1]);
        acc[0][2] = fmaf(r0, w0.z, acc[0][2]); acc[0][3] = fmaf(r0, w0.w, acc[0][3]);
        acc[0][4] = fmaf(r0, w1.x, acc[0][4]); acc[0][5] = fmaf(r0, w1.y, acc[0][5]);
        acc[0][6] = fmaf(r0, w1.z, acc[0][6]); acc[0][7] = fmaf(r0, w1.w, acc[0][7]);
        acc[1][0] = fmaf(r1, w0.x, acc[1][0]); acc[1][1] = fmaf(r1, w0.y, acc[1][1]);
        acc[1][2] = fmaf(r1, w0.z, acc[1][2]); acc[1][3] = fmaf(r1, w0.w, acc[1][3]);
        acc[1][4] = fmaf(r1, w1.x, acc[1][4]); acc[1][5] = fmaf(r1, w1.y, acc[1][5]);
        acc[1][6] = fmaf(r1, w1.z, acc[1][6]); acc[1][7] = fmaf(r1, w1.w, acc[1][7]);
        acc[2][0] = fmaf(r2, w0.x, acc[2][0]); acc[2][1] = fmaf(r2, w0.y, acc[2][1]);
        acc[2][2] = fmaf(r2, w0.z, acc[2][2]); acc[2][3] = fmaf(r2, w0.w, acc[2][3]);
        acc[2][4] = fmaf(r2, w1.x, acc[2][4]); acc[2][5] = fmaf(r2, w1.y, acc[2][5]);
        acc[2][6] = fmaf(r2, w1.z, acc[2][6]); acc[2][7] = fmaf(r2, w1.w, acc[2][7]);
        acc[3][0] = fmaf(r3, w0.x, acc[3][0]); acc[3][1] = fmaf(r3, w0.y, acc[3][1]);
        acc[3][2] = fmaf(r3, w0.z, acc[3][2]); acc[3][3] = fmaf(r3, w0.w, acc[3][3]);
        acc[3][4] = fmaf(r3, w1.x, acc[3][4]); acc[3][5] = fmaf(r3, w1.y, acc[3][5]);
        acc[3][6] = fmaf(r3, w1.z, acc[3][6]); acc[3][7] = fmaf(r3, w1.w, acc[3][7]);
    }

    #pragma unroll
    for (int i = 0; i < 4; i++) {
        int node = base + n0 + i;
        if ((n0 + i) < nv) {
            float d = __ldg(&dv[node]);
            __half2 h0 = __floats2half2_rn(d * acc[i][0], d * acc[i][1]);
            __half2 h1 = __floats2half2_rn(d * acc[i][2], d * acc[i][3]);
            __half2 h2 = __floats2half2_rn(d * acc[i][4], d * acc[i][5]);
            __half2 h3 = __floats2half2_rn(d * acc[i][6], d * acc[i][7]);
            uint4 o;
            o.x = *reinterpret_cast<unsigned*>(&h0);
            o.y = *reinterpret_cast<unsigned*>(&h1);
            o.z = *reinterpret_cast<unsigned*>(&h2);
            o.w = *reinterpret_cast<unsigned*>(&h3);
            *(uint4*)(outh + (size_t)node * HD + jt * 8) = o;
        }
    }
}

// ---------------- final FC (+BN finalize, + cnt re-zero for next call) ----------------
__global__ void __launch_bounds__(128)
fc_kernel(const float* __restrict__ agg, const float* __restrict__ wfc,
          const float* __restrict__ bfc, const float* __restrict__ gg,
          const float* __restrict__ be, float* __restrict__ out, int n) {
    __shared__ float tile[128 * TS];
    __shared__ float Wf[HD * OUTD];
    __shared__ float as[HD], cs[HD];
    int t = threadIdx.x;
    if (t < HD) {
        double mean = g_sum[t] / n;
        double var  = g_sumsq[t] / n - mean * mean;
        float a = gg[t] * rsqrtf((float)var + BN_EPS);
        as[t] = a;
        cs[t] = be[t] - (float)mean * a;
        ((float4*)Wf)[t] = ((const float4*)wfc)[t];
    }

    int base = blockIdx.x * 128;
    // re-zero degree counters for the next kernel_launch invocation
    {
        int i = base + t;
        if (i < n) { g_cnt_s[i] = 0; g_cnt_t[i] = 0; }
    }
    int nv = min(128, n - base);
    const float4* in4 = (const float4*)(agg + (size_t)base * HD);
    for (int i = t; i < nv * 16; i += 128) {
        float4 v = __ldg(&in4[i]);
        float* p = &tile[(i >> 4) * TS + (i & 15) * 4];
        p[0] = v.x; p[1] = v.y; p[2] = v.z; p[3] = v.w;
    }
    __syncthreads();
    if (t < nv) {
        float a0 = __ldg(&bfc[0]), a1 = __ldg(&bfc[1]);
        float a2 = __ldg(&bfc[2]), a3 = __ldg(&bfc[3]);
        const float* row = &tile[t * TS];
        #pragma unroll 8
        for (int k = 0; k < HD; k++) {
            float v = fmaxf(fmaf(row[k], as[k], cs[k]), 0.f);
            a0 = fmaf(v, Wf[k * 4 + 0], a0);
            a1 = fmaf(v, Wf[k * 4 + 1], a1);
            a2 = fmaf(v, Wf[k * 4 + 2], a2);
            a3 = fmaf(v, Wf[k * 4 + 3], a3);
        }
        ((float4*)out)[base + t] = make_float4(a0, a1, a2, a3);
    }
}

// ---------------- host orchestration ----------------
extern "C" void kernel_launch(void* const* d_in, const int* in_sizes, int n_in,
                              void* d_out, int out_size) {
    const float* x   = (const float*)d_in[0];
    const int*   sei = (const int*)d_in[1];
    const int*   tei = (const int*)d_in[2];
    const float* w1  = (const float*)d_in[3];
    const float* b1  = (const float*)d_in[4];
    const float* g1  = (const float*)d_in[5];
    const float* be1 = (const float*)d_in[6];
    const float* w2  = (const float*)d_in[7];
    const float* b2  = (const float*)d_in[8];
    const float* g2  = (const float*)d_in[9];
    const float* be2 = (const float*)d_in[10];
    const float* w3  = (const float*)d_in[11];
    const float* b3  = (const float*)d_in[12];
    const float* g3  = (const float*)d_in[13];
    const float* be3 = (const float*)d_in[14];
    const float* w4  = (const float*)d_in[15];
    const float* b4  = (const float*)d_in[16];
    const float* g4  = (const float*)d_in[17];
    const float* be4 = (const float*)d_in[18];
    const float* wfc = (const float*)d_in[19];
    const float* bfc = (const float*)d_in[20];
    float* out = (float*)d_out;

    const int n = in_sizes[0] / IND;   // 100000
    const int e = in_sizes[1] / 2;     // 1600000
    const int* s_rows = sei;  const int* s_cols = sei + e;
    const int* t_rows = tei;  const int* t_cols = tei + e;

    int *cnt_s, *cnt_t, *start_s, *start_t, *cur_s, *cur_t, *bsum;
    float *dv_s, *dv_t, *agg;
    __half* xwh;
    int *adj_s, *adj_t;
    cudaGetSymbolAddress((void**)&cnt_s, g_cnt_s);
    cudaGetSymbolAddress((void**)&cnt_t, g_cnt_t);
    cudaGetSymbolAddress((void**)&start_s, g_start_s);
    cudaGetSymbolAddress((void**)&start_t, g_start_t);
    cudaGetSymbolAddress((void**)&cur_s, g_cur_s);
    cudaGetSymbolAddress((void**)&cur_t, g_cur_t);
    cudaGetSymbolAddress((void**)&dv_s, g_dv_s);
    cudaGetSymbolAddress((void**)&dv_t, g_dv_t);
    cudaGetSymbolAddress((void**)&xwh, g_xwh);
    cudaGetSymbolAddress((void**)&agg, g_agg);
    cudaGetSymbolAddress((void**)&adj_s, g_adj_s);
    cudaGetSymbolAddress((void**)&adj_t, g_adj_t);
    cudaGetSymbolAddress((void**)&bsum, g_bsum);

    const int eg   = cdiv(e, 256);
    const int ng16 = cdiv((long long)n * 16, 256);
    const int ng8  = cdiv((long long)n * 8, 256);

    // ---- CSR build (merged two-graph kernels; cnt pre-zeroed) ----
    count_kernel<<<eg, 256>>>(s_cols, t_cols, cnt_s, cnt_t, e);
    scan1_kernel<<<dim3(SCAN_NBLK, 2), 1024>>>(cnt_s, start_s, cnt_t, start_t,
                                               dv_s, dv_t, bsum, n);
    scan23_kernel<<<dim3(cdiv(n, 256), 2), 256>>>(start_s, cur_s, start_t, cur_t, bsum, n);
    place_kernel<<<eg, 256>>>(s_rows, s_cols, t_rows, t_cols,
                              cur_s, cur_t, adj_s, adj_t, e);

    // ---- layer 1 (spatial) ----
    xw1_kernel<<<ng16, 256>>>(x, w1, dv_s, xwh, n);
    gather_kernel<<<ng8, 256>>>(adj_s, start_s, cnt_s, dv_s, xwh, b1, agg, n);
    bn_stats_kernel<<<512, 256>>>(agg, n);

    // ---- layer 2 (spatial) ----
    xw_fused_kernel<<<cdiv(n, 64), 128>>>(agg, w2, g1, be1, dv_s, xwh, n);
    gather_kernel<<<ng8, 256>>>(adj_s, start_s, cnt_s, dv_s, xwh, b2, agg, n);
    bn_stats_kernel<<<512, 256>>>(agg, n);

    // ---- layer 3 (temporal) ----
    xw_fused_kernel<<<cdiv(n, 64), 128>>>(agg, w3, g2, be2, dv_t, xwh, n);
    gather_kernel<<<ng8, 256>>>(adj_t, start_t, cnt_t, dv_t, xwh, b3, agg, n);
    bn_stats_kernel<<<512, 256>>>(agg, n);

    // ---- layer 4 (temporal) ----
    xw_fused_kernel<<<cdiv(n, 64), 128>>>(agg, w4, g3, be3, dv_t, xwh, n);
    gather_kernel<<<ng8, 256>>>(adj_t, start_t, cnt_t, dv_t, xwh, b4, agg, n);
    bn_stats_kernel<<<512, 256>>>(agg, n);

    // ---- final FC (+BN finalize of layer 4, + cnt re-zero) ----
    fc_kernel<<<cdiv(n, 128), 128>>>(agg, wfc, bfc, g4, be4, out, n);
}